// round 11
// baseline (speedup 1.0000x reference)
#include <cuda_runtime.h>
#include <cstdint>

typedef unsigned long long ull;
#define NB 32768
#define NL 128

__device__ float g_eps[NL * NB];   // static scratch, allocation-rule safe

__device__ __forceinline__ ull ffma2(ull a, ull b, ull c){
    ull d; asm("fma.rn.f32x2 %0, %1, %2, %3;" : "=l"(d) : "l"(a), "l"(b), "l"(c)); return d;
}
__device__ __forceinline__ ull dup2(float f){
    ull r; asm("mov.b64 %0, {%1, %1};" : "=l"(r) : "f"(f)); return r;
}
__device__ __forceinline__ float2 unpack2(ull v){
    float2 r; asm("mov.b64 {%0, %1}, %2;" : "=f"(r.x), "=f"(r.y) : "l"(v)); return r;
}
__device__ __forceinline__ float sigf(float x){ return __fdividef(1.0f, 1.0f + __expf(-x)); }
__device__ __forceinline__ float tanh_f(float x){
    float e = __expf(2.0f * x); return 1.0f - __fdividef(2.0f, 1.0f + e);
}

// JAX threefry2x32, key=(0,42), partitionable: counter=(0,i), 32-bit fold x0^x1
#define TFR(r) { x0 += x1; x1 = __funnelshift_l(x1, x1, (r)); x1 ^= x0; }
__device__ __forceinline__ uint32_t tf_bits(uint32_t i){
    const uint32_t K0 = 0u, K1 = 42u, K2 = 0x1BD11BDAu ^ 42u;
    uint32_t x0 = K0, x1 = i + K1;
    TFR(13) TFR(15) TFR(26) TFR(6)  x0 += K1; x1 += K2 + 1u;
    TFR(17) TFR(29) TFR(16) TFR(24) x0 += K2; x1 += K0 + 2u;
    TFR(13) TFR(15) TFR(26) TFR(6)  x0 += K0; x1 += K1 + 3u;
    TFR(17) TFR(29) TFR(16) TFR(24) x0 += K1; x1 += K2 + 4u;
    TFR(13) TFR(15) TFR(26) TFR(6)  x0 += K2; x1 += K0 + 5u;
    return x0 ^ x1;
}
__device__ __forceinline__ float erfinv_f(float x){
    float w = -__logf(fmaf(x, -x, 1.0f)), p;
    if (w < 5.0f){
        w -= 2.5f;
        p = 2.81022636e-08f;
        p = fmaf(p, w, 3.43273939e-07f);  p = fmaf(p, w, -3.5233877e-06f);
        p = fmaf(p, w, -4.39150654e-06f); p = fmaf(p, w, 0.00021858087f);
        p = fmaf(p, w, -0.00125372503f);  p = fmaf(p, w, -0.00417768164f);
        p = fmaf(p, w, 0.246640727f);     p = fmaf(p, w, 1.50140941f);
    } else {
        w = __fsqrt_rn(w) - 3.0f;
        p = -0.000200214257f;
        p = fmaf(p, w, 0.000100950558f);  p = fmaf(p, w, 0.00134934322f);
        p = fmaf(p, w, -0.00367342844f);  p = fmaf(p, w, 0.00573950773f);
        p = fmaf(p, w, -0.0076224613f);   p = fmaf(p, w, 0.00943887047f);
        p = fmaf(p, w, 1.00167406f);      p = fmaf(p, w, 2.83297682f);
    }
    return p * x;
}
__global__ void eps_kernel(){
    uint32_t i = blockIdx.x * 256u + threadIdx.x;
    uint32_t bits = tf_bits(i);
    float u01 = __uint_as_float((bits >> 9) | 0x3f800000u) - 1.0f;
    const float mn = __uint_as_float(0xBF7FFFFFu);          // -0.99999994
    float u = fmaxf(mn, fmaf(u01, 2.0f, mn));
    g_eps[i] = __uint_as_float(0x3FB504F3u) * erfinv_f(u);  // sqrt(2)f * erfinv(u)
}

struct __align__(16) Smem {
    float2 X[127*40];  // W_ih1 col c: [c*40+j]=(Wi_j,Wf_j), [c*40+20+j]=(Wg_j,Wo_j)
    float2 WIF[400];   // [j*20+d]=(Whh1[j][d], Whh1[20+j][d])
    float2 WGO[400];   // [j*20+d]=(Whh1[40+j][d], Whh1[60+j][d])
    float2 W2[160];    // [p*40+d]=(Wih2[2p][d], Wih2[2p+1][d])
    float2 Wh2[8];     // [p*2+e]=(Whh2[2p][e], Whh2[2p+1][e])
    float2 B2[4];
    float2 BIF[20];
    float2 BGO[20];
};

__global__ void __launch_bounds__(256, 1) lstm_kernel(
    const float* __restrict__ mu,   const float* __restrict__ log_var,
    const float* __restrict__ Wih1, const float* __restrict__ Whh1,
    const float* __restrict__ bih1, const float* __restrict__ bhh1,
    const float* __restrict__ Wih2, const float* __restrict__ Whh2,
    const float* __restrict__ bih2, const float* __restrict__ bhh2,
    float* __restrict__ out)
{
    __shared__ Smem sm;
    const int tid = threadIdx.x;

    for (int idx = tid; idx < 127*40; idx += 256){
        int c = idx / 40, q = idx - c*40;
        int j  = (q < 20) ? q : (q - 20);
        int r0 = (q < 20) ? j : (40 + j);
        int r1 = (q < 20) ? (20 + j) : (60 + j);
        sm.X[idx] = make_float2(Wih1[r0*127 + c], Wih1[r1*127 + c]);
    }
    for (int idx = tid; idx < 400; idx += 256){
        int j = idx / 20, d = idx - j*20;
        sm.WIF[idx] = make_float2(Whh1[j*20 + d],      Whh1[(20+j)*20 + d]);
        sm.WGO[idx] = make_float2(Whh1[(40+j)*20 + d], Whh1[(60+j)*20 + d]);
    }
    if (tid < 160){
        int p = tid / 40, d = tid - p*40;
        sm.W2[tid] = make_float2(Wih2[(2*p)*40 + d], Wih2[(2*p+1)*40 + d]);
    }
    if (tid < 8){
        int p = tid >> 1, e = tid & 1;
        sm.Wh2[tid] = make_float2(Whh2[(2*p)*2 + e], Whh2[(2*p+1)*2 + e]);
    }
    if (tid < 4)
        sm.B2[tid] = make_float2(bih2[2*tid] + bhh2[2*tid], bih2[2*tid+1] + bhh2[2*tid+1]);
    if (tid < 20){
        sm.BIF[tid] = make_float2(bih1[tid]    + bhh1[tid],    bih1[20+tid] + bhh1[20+tid]);
        sm.BGO[tid] = make_float2(bih1[40+tid] + bhh1[40+tid], bih1[60+tid] + bhh1[60+tid]);
    }
    __syncthreads();

    const int b = blockIdx.x * 256 + tid;
    const float* muRow = mu + b * NL;
    float* outMu = out + b * NL;
    float* outLv = out + (NB * NL)     + b * NL;
    float* outS  = out + 2 * (NB * NL) + b * NL;

    ull aIF[20], aGO[20], hp[20];
    float c1[20];
    const ull* uBIF = reinterpret_cast<const ull*>(sm.BIF);
    const ull* uBGO = reinterpret_cast<const ull*>(sm.BGO);
#pragma unroll
    for (int j = 0; j < 20; ++j){ aIF[j]=uBIF[j]; aGO[j]=uBGO[j]; hp[j]=0ull; c1[j]=0.0f; }
    float h2x=0.f, h2y=0.f, c2x=0.f, c2y=0.f;

    const float mu0  = muRow[0];
    const float lv0  = log_var[b * NL];
    const float eps0 = g_eps[b];
    const float first = fmaf(eps0, __expf(0.5f * lv0), mu0);
    outMu[0] = 0.0f; outLv[0] = 1.0f; outS[0] = first;

    const ulonglong2* X2 = reinterpret_cast<const ulonglong2*>(sm.X);
    {   // step-1 x-proj: col 0 * first_input
        ull fp = dup2(first);
#pragma unroll
        for (int q = 0; q < 10; ++q){
            ulonglong2 w = X2[q];
            aIF[2*q]   = ffma2(fp, w.x, aIF[2*q]);
            aIF[2*q+1] = ffma2(fp, w.y, aIF[2*q+1]);
        }
#pragma unroll
        for (int q = 0; q < 10; ++q){
            ulonglong2 w = X2[10+q];
            aGO[2*q]   = ffma2(fp, w.x, aGO[2*q]);
            aGO[2*q+1] = ffma2(fp, w.y, aGO[2*q+1]);
        }
    }

    const ull* uW2  = reinterpret_cast<const ull*>(sm.W2);
    const ull* uWh2 = reinterpret_cast<const ull*>(sm.Wh2);
    const ull* uB2  = reinterpret_cast<const ull*>(sm.B2);

#pragma unroll 1
    for (int t = 1; t < NL; ++t){
        float hn[20];
#pragma unroll
        for (int j = 0; j < 20; ++j){
            ull gIF = aIF[j], gGO = aGO[j];
            const ulonglong2* wIF = reinterpret_cast<const ulonglong2*>(sm.WIF + j*20);
            const ulonglong2* wGO = reinterpret_cast<const ulonglong2*>(sm.WGO + j*20);
#pragma unroll
            for (int q = 0; q < 10; ++q){
                ulonglong2 wa = wIF[q], wb = wGO[q];
                gIF = ffma2(hp[2*q],   wa.x, gIF);
                gIF = ffma2(hp[2*q+1], wa.y, gIF);
                gGO = ffma2(hp[2*q],   wb.x, gGO);
                gGO = ffma2(hp[2*q+1], wb.y, gGO);
            }
            float2 vif = unpack2(gIF), vgo = unpack2(gGO);
            float ig = sigf(vif.x), fg = sigf(vif.y);
            float gg = tanh_f(vgo.x), og = sigf(vgo.y);
            float cn = fmaf(fg, c1[j], ig * gg);
            c1[j] = cn;
            hn[j] = og * tanh_f(cn);
        }

        ull G0 = uB2[0], G1 = uB2[1], G2 = uB2[2], G3 = uB2[3];
#pragma unroll
        for (int d = 0; d < 20; ++d){
            float v = hn[d];
            ull lp = dup2(fmaxf(v, 0.01f * v));
            G0 = ffma2(lp, uW2[d],       G0);
            G1 = ffma2(lp, uW2[40 + d],  G1);
            G2 = ffma2(lp, uW2[80 + d],  G2);
            G3 = ffma2(lp, uW2[120 + d], G3);
        }
#pragma unroll
        for (int d = 0; d < 20; ++d){
            float v = c1[d];
            ull lp = dup2(fmaxf(v, 0.01f * v));
            G0 = ffma2(lp, uW2[20 + d],  G0);
            G1 = ffma2(lp, uW2[60 + d],  G1);
            G2 = ffma2(lp, uW2[100 + d], G2);
            G3 = ffma2(lp, uW2[140 + d], G3);
        }
        {
            ull hx = dup2(h2x), hy = dup2(h2y);
            G0 = ffma2(hx, uWh2[0], G0); G0 = ffma2(hy, uWh2[1], G0);
            G1 = ffma2(hx, uWh2[2], G1); G1 = ffma2(hy, uWh2[3], G1);
            G2 = ffma2(hx, uWh2[4], G2); G2 = ffma2(hy, uWh2[5], G2);
            G3 = ffma2(hx, uWh2[6], G3); G3 = ffma2(hy, uWh2[7], G3);
        }
        float2 gi = unpack2(G0), gf = unpack2(G1), gg2 = unpack2(G2), go = unpack2(G3);
        float i0 = sigf(gi.x),    i1 = sigf(gi.y);
        float f0 = sigf(gf.x),    f1 = sigf(gf.y);
        float t0 = tanh_f(gg2.x), t1 = tanh_f(gg2.y);
        float o0 = sigf(go.x),    o1 = sigf(go.y);
        c2x = fmaf(f0, c2x, i0 * t0);
        c2y = fmaf(f1, c2y, i1 * t1);
        h2x = o0 * tanh_f(c2x);
        h2y = o1 * tanh_f(c2y);

        float eps_t = g_eps[t * NB + b];
        outMu[t] = h2x;
        outLv[t] = h2y;
        outS[t]  = fmaf(eps_t, __expf(0.5f * h2y), h2x);

#pragma unroll
        for (int j = 0; j < 20; ++j) hp[j] = dup2(hn[j]);

        if (t < 127){
            ull mp = dup2(muRow[t]);
            const ulonglong2* xc = X2 + t * 20;
#pragma unroll
            for (int q = 0; q < 10; ++q){
                ulonglong2 w = xc[q];
                aIF[2*q]   = ffma2(mp, w.x, aIF[2*q]);
                aIF[2*q+1] = ffma2(mp, w.y, aIF[2*q+1]);
            }
#pragma unroll
            for (int q = 0; q < 10; ++q){
                ulonglong2 w = xc[10+q];
                aGO[2*q]   = ffma2(mp, w.x, aGO[2*q]);
                aGO[2*q+1] = ffma2(mp, w.y, aGO[2*q+1]);
            }
            if (t == 1){   // col 0 switches first_input -> mu[:,0] after step 1
                ull dp = dup2(mu0 - first);
#pragma unroll
                for (int q = 0; q < 10; ++q){
                    ulonglong2 w = X2[q];
                    aIF[2*q]   = ffma2(dp, w.x, aIF[2*q]);
                    aIF[2*q+1] = ffma2(dp, w.y, aIF[2*q+1]);
                }
#pragma unroll
                for (int q = 0; q < 10; ++q){
                    ulonglong2 w = X2[10+q];
                    aGO[2*q]   = ffma2(dp, w.x, aGO[2*q]);
                    aGO[2*q+1] = ffma2(dp, w.y, aGO[2*q+1]);
                }
            }
        }
    }
}

extern "C" void kernel_launch(void* const* d_in, const int* in_sizes, int n_in,
                              void* d_out, int out_size){
    (void)in_sizes; (void)n_in; (void)out_size;
    eps_kernel<<<(NL * NB) / 256, 256>>>();
    lstm_kernel<<<NB / 256, 256>>>(
        (const float*)d_in[0], (const float*)d_in[1],
        (const float*)d_in[2], (const float*)d_in[3],
        (const float*)d_in[4], (const float*)d_in[5],
        (const float*)d_in[6], (const float*)d_in[7],
        (const float*)d_in[8], (const float*)d_in[9],
        (float*)d_out);
}